// round 2
// baseline (speedup 1.0000x reference)
#include <cuda_runtime.h>
#include <cstdint>

#define DIMC     1024
#define HEADS    16
#define HEAD_DIM 64
#define NTOK     49
#define BATCH    1024
#define MROWS    (BATCH * NTOK)   // 50176
#define SCALE    0.125f           // 64^-0.5

// ---------------- scratch (device globals: allocation-free) ----------------
__device__ float g_Q[(size_t)MROWS * DIMC];
__device__ float g_K[(size_t)MROWS * DIMC];
__device__ float g_V[(size_t)MROWS * DIMC];

// ---------------- helpers ----------------
__device__ __forceinline__ unsigned f2tf(float x) {
    unsigned r;
    asm("cvt.rna.tf32.f32 %0, %1;" : "=r"(r) : "f"(x));
    return r;
}

__device__ __forceinline__ void mma_tf32(float c[4],
                                         unsigned a0, unsigned a1, unsigned a2, unsigned a3,
                                         unsigned b0, unsigned b1) {
    asm volatile(
        "mma.sync.aligned.m16n8k8.row.col.f32.tf32.tf32.f32 "
        "{%0,%1,%2,%3}, {%4,%5,%6,%7}, {%8,%9}, {%0,%1,%2,%3};\n"
        : "+f"(c[0]), "+f"(c[1]), "+f"(c[2]), "+f"(c[3])
        : "r"(a0), "r"(a1), "r"(a2), "r"(a3), "r"(b0), "r"(b1));
}

__device__ __forceinline__ void cp_async16(uint32_t saddr, const void* g) {
    asm volatile("cp.async.cg.shared.global [%0], [%1], 16;\n" :: "r"(saddr), "l"(g) : "memory");
}
__device__ __forceinline__ void cp_commit() {
    asm volatile("cp.async.commit_group;\n" ::: "memory");
}
__device__ __forceinline__ void cp_wait0() {
    asm volatile("cp.async.wait_group 0;\n" ::: "memory");
}

// ---------------- TF32 GEMM: Y[M,1024] = X[M,1024] @ W[1024,1024]^T + bias ----------------
#define BM 128
#define BN 128
#define BK 16
#define PADK 20   // smem row stride in floats (conflict-free for frag reads)

__global__ __launch_bounds__(256) void gemm_tf32_kernel(
    const float* __restrict__ X_ext, const float* __restrict__ W,
    const float* __restrict__ bias, float* __restrict__ Y_ext,
    int xsel, int ysel)
{
    // selector avoids any host-side symbol-address lookup
    const float* X = (xsel == 0) ? X_ext : (const float*)g_Q;
    float* Y = Y_ext;
    if (ysel == 1) Y = g_Q; else if (ysel == 2) Y = g_K; else if (ysel == 3) Y = g_V;

    __shared__ __align__(16) float As[2][BM * PADK];
    __shared__ __align__(16) float Bs[2][BN * PADK];

    const int tid  = threadIdx.x;
    const int warp = tid >> 5;
    const int lane = tid & 31;
    const int wm   = warp >> 2;   // 0..1
    const int wn   = warp & 3;    // 0..3
    const int m0g  = blockIdx.y * BM;
    const int n0g  = blockIdx.x * BN;

    float acc[4][4][4];
#pragma unroll
    for (int mi = 0; mi < 4; ++mi)
#pragma unroll
        for (int ni = 0; ni < 4; ++ni)
#pragma unroll
            for (int r = 0; r < 4; ++r) acc[mi][ni][r] = 0.f;

    const uint32_t sA = (uint32_t)__cvta_generic_to_shared(&As[0][0]);
    const uint32_t sB = (uint32_t)__cvta_generic_to_shared(&Bs[0][0]);

    // tile load: 128x16 floats from each of X and W
    auto load_tile = [&](int buf, int kt) {
#pragma unroll
        for (int i = 0; i < 2; ++i) {
            int id  = tid + i * 256;          // 0..511
            int row = id >> 2;                // 0..127
            int c4  = (id & 3) << 2;          // 0,4,8,12
            uint32_t so = (uint32_t)((buf * BM * PADK + row * PADK + c4) * 4);
            cp_async16(sA + so, X + (size_t)(m0g + row) * DIMC + kt * BK + c4);
            cp_async16(sB + so, W + (size_t)(n0g + row) * DIMC + kt * BK + c4);
        }
        cp_commit();
    };

    load_tile(0, 0);

    const int KT = DIMC / BK;   // 64
    for (int kt = 0; kt < KT; ++kt) {
        cp_wait0();
        __syncthreads();
        int buf = kt & 1;
        if (kt + 1 < KT) load_tile(buf ^ 1, kt + 1);

        const float* Asb = &As[buf][0];
        const float* Bsb = &Bs[buf][0];
#pragma unroll
        for (int kk = 0; kk < BK; kk += 8) {
            unsigned af[4][4];
            unsigned bf[4][2];
#pragma unroll
            for (int mi = 0; mi < 4; ++mi) {
                int r = wm * 64 + mi * 16 + (lane >> 2);
                int c = kk + (lane & 3);
                af[mi][0] = f2tf(Asb[r * PADK + c]);
                af[mi][1] = f2tf(Asb[(r + 8) * PADK + c]);
                af[mi][2] = f2tf(Asb[r * PADK + c + 4]);
                af[mi][3] = f2tf(Asb[(r + 8) * PADK + c + 4]);
            }
#pragma unroll
            for (int ni = 0; ni < 4; ++ni) {
                int rn = wn * 32 + ni * 8 + (lane >> 2);
                int c  = kk + (lane & 3);
                bf[ni][0] = f2tf(Bsb[rn * PADK + c]);
                bf[ni][1] = f2tf(Bsb[rn * PADK + c + 4]);
            }
#pragma unroll
            for (int mi = 0; mi < 4; ++mi)
#pragma unroll
                for (int ni = 0; ni < 4; ++ni)
                    mma_tf32(acc[mi][ni], af[mi][0], af[mi][1], af[mi][2], af[mi][3],
                             bf[ni][0], bf[ni][1]);
        }
    }

    // epilogue: + bias, float2 stores
#pragma unroll
    for (int mi = 0; mi < 4; ++mi) {
        int r0 = m0g + wm * 64 + mi * 16 + (lane >> 2);
#pragma unroll
        for (int ni = 0; ni < 4; ++ni) {
            int cc = n0g + wn * 32 + ni * 8 + ((lane & 3) << 1);
            float bv0 = bias[cc], bv1 = bias[cc + 1];
            float2 v0 = make_float2(acc[mi][ni][0] + bv0, acc[mi][ni][1] + bv1);
            float2 v1 = make_float2(acc[mi][ni][2] + bv0, acc[mi][ni][3] + bv1);
            *(float2*)&Y[(size_t)r0 * DIMC + cc]       = v0;
            *(float2*)&Y[(size_t)(r0 + 8) * DIMC + cc] = v1;
        }
    }
}

// ---------------- fused windowed attention per (b,h) ----------------
// scores = (q k^T)*scale + bias[h]; softmax; out = p v  -> written into g_Q slice
__global__ __launch_bounds__(256) void attn_kernel(
    const float* __restrict__ bias_table, const int* __restrict__ rel_idx)
{
    __shared__ float sq[NTOK * 64];
    __shared__ float sv[NTOK * 64];
    __shared__ float sk[NTOK * 65];      // odd stride: conflict-free over j
    __shared__ float sp[NTOK * NTOK];    // bias, then probs (reused)

    const int b = blockIdx.x;
    const int h = blockIdx.y;
    const int tid  = threadIdx.x;
    const int warp = tid >> 5;
    const int lane = tid & 31;

    const size_t base = (size_t)(b * NTOK) * DIMC + h * HEAD_DIM;

    // load q,k,v tiles (float4)
    for (int t = tid; t < NTOK * 16; t += 256) {
        int row = t >> 4;
        int c4  = (t & 15) << 2;
        float4 qv = *(const float4*)&g_Q[base + (size_t)row * DIMC + c4];
        float4 kv = *(const float4*)&g_K[base + (size_t)row * DIMC + c4];
        float4 vv = *(const float4*)&g_V[base + (size_t)row * DIMC + c4];
        *(float4*)&sq[row * 64 + c4] = qv;
        *(float4*)&sv[row * 64 + c4] = vv;
        sk[row * 65 + c4 + 0] = kv.x;
        sk[row * 65 + c4 + 1] = kv.y;
        sk[row * 65 + c4 + 2] = kv.z;
        sk[row * 65 + c4 + 3] = kv.w;
    }
    // gather relative-position bias for this head
    for (int t = tid; t < NTOK * NTOK; t += 256)
        sp[t] = bias_table[rel_idx[t] * HEADS + h];
    __syncthreads();

    // scores + softmax: one warp per query row
    for (int i = warp; i < NTOK; i += 8) {
        const float* qi = &sq[i * 64];
        int j1 = lane;
        int j2 = lane + 32;
        int j2c = (j2 < NTOK) ? j2 : 0;
        const float* k1 = &sk[j1 * 65];
        const float* k2 = &sk[j2c * 65];
        float s1 = 0.f, s2 = 0.f;
#pragma unroll
        for (int d = 0; d < 64; ++d) {
            float qd = qi[d];
            s1 = fmaf(qd, k1[d], s1);
            s2 = fmaf(qd, k2[d], s2);
        }
        s1 = s1 * SCALE + sp[i * NTOK + j1];
        float s2v = (j2 < NTOK) ? (s2 * SCALE + sp[i * NTOK + j2]) : -1e30f;

        float m = fmaxf(s1, s2v);
#pragma unroll
        for (int off = 16; off > 0; off >>= 1)
            m = fmaxf(m, __shfl_xor_sync(0xFFFFFFFFu, m, off));
        float e1 = __expf(s1 - m);
        float e2 = (j2 < NTOK) ? __expf(s2v - m) : 0.f;
        float sum = e1 + e2;
#pragma unroll
        for (int off = 16; off > 0; off >>= 1)
            sum += __shfl_xor_sync(0xFFFFFFFFu, sum, off);
        float inv = 1.f / sum;
        sp[i * NTOK + j1] = e1 * inv;
        if (j2 < NTOK) sp[i * NTOK + j2] = e2 * inv;
    }
    __syncthreads();

    // out[i][d] = sum_j p[i][j] * v[j][d]; write back into g_Q slice
    for (int t = tid; t < NTOK * 64; t += 256) {
        int i = t >> 6;
        int d = t & 63;
        const float* pi = &sp[i * NTOK];
        float a = 0.f;
#pragma unroll
        for (int j = 0; j < NTOK; ++j)
            a = fmaf(pi[j], sv[j * 64 + d], a);
        g_Q[base + (size_t)i * DIMC + d] = a;
    }
}

// ---------------- launch ----------------
extern "C" void kernel_launch(void* const* d_in, const int* in_sizes, int n_in,
                              void* d_out, int out_size) {
    const float* landmark = (const float*)d_in[0];
    const float* image    = (const float*)d_in[1];
    const float* Wq = (const float*)d_in[2];
    const float* bq = (const float*)d_in[3];
    const float* Wk = (const float*)d_in[4];
    const float* bk = (const float*)d_in[5];
    const float* Wv = (const float*)d_in[6];
    const float* bv = (const float*)d_in[7];
    const float* Wo = (const float*)d_in[8];
    const float* bo = (const float*)d_in[9];
    const float* bt = (const float*)d_in[10];
    const int*   ri = (const int*)d_in[11];
    float* out = (float*)d_out;

    dim3 gg(DIMC / BN, MROWS / BM);   // (8, 392)

    // projections -> scratch
    gemm_tf32_kernel<<<gg, 256>>>(landmark, Wq, bq, nullptr, 0, 1);  // Q
    gemm_tf32_kernel<<<gg, 256>>>(image,    Wk, bk, nullptr, 0, 2);  // K
    gemm_tf32_kernel<<<gg, 256>>>(image,    Wv, bv, nullptr, 0, 3);  // V

    // attention (writes result back into g_Q)
    attn_kernel<<<dim3(BATCH, HEADS), 256>>>(bt, ri);

    // output projection from g_Q -> d_out
    gemm_tf32_kernel<<<gg, 256>>>(nullptr, Wo, bo, out, 1, 0);
}

// round 4
// speedup vs baseline: 1.1043x; 1.1043x over previous
#include <cuda_runtime.h>
#include <cuda_fp16.h>
#include <cstdint>

#define DIMC   1024
#define HEADS  16
#define NTOK   49
#define BATCH  1024
#define MROWS  (BATCH * NTOK)   // 50176
#define SCALE  0.125f

// ---------------- half scratch (device globals) ----------------
__device__ __half g_A[(size_t)MROWS * DIMC];     // landmark half
__device__ __half g_B[(size_t)MROWS * DIMC];     // image half, later attn output
__device__ __half g_Q[(size_t)MROWS * DIMC];
__device__ __half g_K[(size_t)MROWS * DIMC];
__device__ __half g_V[(size_t)MROWS * DIMC];
__device__ __half g_Wh[4 * (size_t)DIMC * DIMC]; // Wq,Wk,Wv,Wo half
__device__ float  g_bias[HEADS * NTOK * NTOK];

// ---------------- fp32 -> fp16 conversion ----------------
__global__ void f2h(const float* __restrict__ src, int dsel, int n) {
    __half* dst = (dsel == 0) ? g_A : (dsel == 1) ? g_B
                : g_Wh + (size_t)(dsel - 2) * DIMC * DIMC;
    int i = blockIdx.x * blockDim.x + threadIdx.x;
    int stride = gridDim.x * blockDim.x;
    for (int t = i; t < n / 4; t += stride) {
        float4 v = ((const float4*)src)[t];
        __half2 h0 = __floats2half2_rn(v.x, v.y);
        __half2 h1 = __floats2half2_rn(v.z, v.w);
        uint2 u;
        u.x = *(uint32_t*)&h0;
        u.y = *(uint32_t*)&h1;
        ((uint2*)dst)[t] = u;
    }
}

// ---------------- cp.async ----------------
__device__ __forceinline__ void cp_async16(uint32_t saddr, const void* g) {
    asm volatile("cp.async.cg.shared.global [%0], [%1], 16;\n" :: "r"(saddr), "l"(g) : "memory");
}
__device__ __forceinline__ void cp_commit() { asm volatile("cp.async.commit_group;\n" ::: "memory"); }
__device__ __forceinline__ void cp_wait1() { asm volatile("cp.async.wait_group 1;\n" ::: "memory"); }

__device__ __forceinline__ void mma_f16(float c[4], uint32_t a0, uint32_t a1, uint32_t a2,
                                        uint32_t a3, uint32_t b0, uint32_t b1) {
    asm volatile(
        "mma.sync.aligned.m16n8k16.row.col.f32.f16.f16.f32 "
        "{%0,%1,%2,%3}, {%4,%5,%6,%7}, {%8,%9}, {%0,%1,%2,%3};\n"
        : "+f"(c[0]), "+f"(c[1]), "+f"(c[2]), "+f"(c[3])
        : "r"(a0), "r"(a1), "r"(a2), "r"(a3), "r"(b0), "r"(b1));
}

// swizzled smem read: row of 128B (64 halves), granule XOR (row&7)
__device__ __forceinline__ uint32_t ldsm(const uint8_t* base, int row, int ch) {
    return *(const uint32_t*)(base + row * 128 + (((ch >> 3) ^ (row & 7)) << 4) + ((ch & 7) * 2));
}

// ---------------- FP16 GEMM: Y[M,1024] = X @ W^T + bias ----------------
#define BM 128
#define BN 128
#define BKH 64                     // K halves per tile (128B rows)
#define NKT (DIMC / BKH)           // 16
#define TILE_A (BM * 128)          // 16384 B
#define SLOT (2 * TILE_A)          // 32768 B
#define SMEMSZ (3 * SLOT)          // 98304 B

__global__ __launch_bounds__(256) void gemm_h(
    const float* __restrict__ bias, float* __restrict__ Yf,
    int xsel, int wsel, int ysel)
{
    extern __shared__ __align__(128) uint8_t smem[];
    const __half* X = xsel ? g_B : g_A;
    const __half* W = g_Wh + (size_t)wsel * DIMC * DIMC;
    __half* Yh = (ysel == 1) ? g_Q : (ysel == 2) ? g_K : g_V;

    const int tid = threadIdx.x, wid = tid >> 5, lane = tid & 31;
    const int wm = wid >> 2, wn = wid & 3;
    const int m0 = blockIdx.y * BM, n0 = blockIdx.x * BN;
    const uint32_t sbase = (uint32_t)__cvta_generic_to_shared(smem);

    float acc[4][4][4];
#pragma unroll
    for (int a = 0; a < 4; ++a)
#pragma unroll
        for (int b = 0; b < 4; ++b)
#pragma unroll
            for (int c = 0; c < 4; ++c) acc[a][b][c] = 0.f;

    const int row = tid >> 1;
    const int g0 = (tid & 1) * 4;
    const int sw = row & 7;

    auto load_stage = [&](int slot, int kt) {
        const __half* xa = X + (size_t)(m0 + row) * DIMC + kt * BKH;
        const __half* xb = W + (size_t)(n0 + row) * DIMC + kt * BKH;
        uint32_t sa = sbase + slot * SLOT + row * 128;
        uint32_t sb = sa + TILE_A;
#pragma unroll
        for (int q = 0; q < 4; ++q) {
            int g = g0 + q;
            uint32_t off = (uint32_t)((g ^ sw) << 4);
            cp_async16(sa + off, xa + g * 8);
            cp_async16(sb + off, xb + g * 8);
        }
        cp_commit();
    };

    load_stage(0, 0);
    load_stage(1, 1);

    const int r8 = lane >> 2, cp2 = (lane & 3) * 2;

    for (int kt = 0; kt < NKT; ++kt) {
        cp_wait1();
        __syncthreads();
        if (kt + 2 < NKT) load_stage((kt + 2) % 3, kt + 2);

        const uint8_t* As = smem + (kt % 3) * SLOT;
        const uint8_t* Bs = As + TILE_A;
#pragma unroll
        for (int ks = 0; ks < 4; ++ks) {
            int ch = ks * 16 + cp2;
            uint32_t a[4][4], b[4][2];
#pragma unroll
            for (int mi = 0; mi < 4; ++mi) {
                int r = wm * 64 + mi * 16 + r8;
                a[mi][0] = ldsm(As, r, ch);
                a[mi][1] = ldsm(As, r + 8, ch);
                a[mi][2] = ldsm(As, r, ch + 8);
                a[mi][3] = ldsm(As, r + 8, ch + 8);
            }
#pragma unroll
            for (int ni = 0; ni < 4; ++ni) {
                int rn = wn * 32 + ni * 8 + r8;
                b[ni][0] = ldsm(Bs, rn, ch);
                b[ni][1] = ldsm(Bs, rn, ch + 8);
            }
#pragma unroll
            for (int mi = 0; mi < 4; ++mi)
#pragma unroll
                for (int ni = 0; ni < 4; ++ni)
                    mma_f16(acc[mi][ni], a[mi][0], a[mi][1], a[mi][2], a[mi][3],
                            b[ni][0], b[ni][1]);
        }
        __syncthreads();
    }

    // epilogue
#pragma unroll
    for (int mi = 0; mi < 4; ++mi) {
        int r = m0 + wm * 64 + mi * 16 + r8;
#pragma unroll
        for (int ni = 0; ni < 4; ++ni) {
            int cc = n0 + wn * 32 + ni * 8 + cp2;
            float b0 = bias[cc], b1 = bias[cc + 1];
            float v0 = acc[mi][ni][0] + b0, v1 = acc[mi][ni][1] + b1;
            float v2 = acc[mi][ni][2] + b0, v3 = acc[mi][ni][3] + b1;
            if (ysel == 0) {
                *(float2*)&Yf[(size_t)r * DIMC + cc]       = make_float2(v0, v1);
                *(float2*)&Yf[(size_t)(r + 8) * DIMC + cc] = make_float2(v2, v3);
            } else {
                __half2 h0 = __floats2half2_rn(v0, v1);
                __half2 h1 = __floats2half2_rn(v2, v3);
                *(__half2*)&Yh[(size_t)r * DIMC + cc]       = h0;
                *(__half2*)&Yh[(size_t)(r + 8) * DIMC + cc] = h1;
            }
        }
    }
}

// ---------------- bias precompute ----------------
__global__ void bias_gather(const float* __restrict__ bt, const int* __restrict__ ri) {
    int t = blockIdx.x * 256 + threadIdx.x;
    if (t < NTOK * NTOK) {
        int idx = ri[t] * HEADS;
#pragma unroll
        for (int h = 0; h < HEADS; ++h)
            g_bias[h * (NTOK * NTOK) + t] = bt[idx + h];
    }
}

// ---------------- fused windowed attention per (b,h), half IO ----------------
__global__ __launch_bounds__(256) void attn_kernel() {
    __shared__ __half   sq[NTOK * 64];
    __shared__ __half2  skT[32 * 56];    // [d2][j], stride 56
    __shared__ __half   sv[NTOK * 64];
    __shared__ float    sp[NTOK * NTOK];

    const int b = blockIdx.x, h = blockIdx.y;
    const int tid = threadIdx.x, warp = tid >> 5, lane = tid & 31;
    const size_t base = (size_t)(b * NTOK) * DIMC + h * 64;

    for (int t = tid; t < NTOK * 8; t += 256) {
        int row = t >> 3, g = t & 7;
        *(uint4*)&sq[row * 64 + g * 8] = *(const uint4*)&g_Q[base + (size_t)row * DIMC + g * 8];
        *(uint4*)&sv[row * 64 + g * 8] = *(const uint4*)&g_V[base + (size_t)row * DIMC + g * 8];
        uint4 kk = *(const uint4*)&g_K[base + (size_t)row * DIMC + g * 8];
        const __half2* kp = (const __half2*)&kk;
#pragma unroll
        for (int w = 0; w < 4; ++w) skT[(g * 4 + w) * 56 + row] = kp[w];
    }
    const float* gb = &g_bias[h * (NTOK * NTOK)];
    for (int t = tid; t < NTOK * NTOK; t += 256) sp[t] = gb[t];
    __syncthreads();

    for (int i = warp; i < NTOK; i += 8) {
        const __half2* qp = (const __half2*)&sq[i * 64];
        int j1 = lane, j2 = lane + 32;
        bool has2 = (j2 < NTOK);
        int j2c = has2 ? j2 : 0;
        float s1 = 0.f, s2 = 0.f;
#pragma unroll
        for (int d2 = 0; d2 < 32; ++d2) {
            float2 q  = __half22float2(qp[d2]);
            float2 k1 = __half22float2(skT[d2 * 56 + j1]);
            float2 k2 = __half22float2(skT[d2 * 56 + j2c]);
            s1 = fmaf(q.x, k1.x, fmaf(q.y, k1.y, s1));
            s2 = fmaf(q.x, k2.x, fmaf(q.y, k2.y, s2));
        }
        s1 = s1 * SCALE + sp[i * NTOK + j1];
        float s2v = has2 ? (s2 * SCALE + sp[i * NTOK + j2]) : -1e30f;

        float m = fmaxf(s1, s2v);
#pragma unroll
        for (int o = 16; o > 0; o >>= 1) m = fmaxf(m, __shfl_xor_sync(0xFFFFFFFFu, m, o));
        float e1 = __expf(s1 - m);
        float e2 = has2 ? __expf(s2v - m) : 0.f;
        float sum = e1 + e2;
#pragma unroll
        for (int o = 16; o > 0; o >>= 1) sum += __shfl_xor_sync(0xFFFFFFFFu, sum, o);
        float inv = 1.f / sum;
        sp[i * NTOK + j1] = e1 * inv;
        if (has2) sp[i * NTOK + j2] = e2 * inv;
    }
    __syncthreads();

    // out = P @ V -> g_B (half)
    for (int t = tid; t < NTOK * 16; t += 256) {
        int i = t >> 4, d4 = (t & 15) * 4;
        const float* pi = &sp[i * NTOK];
        float4 a = make_float4(0.f, 0.f, 0.f, 0.f);
#pragma unroll 7
        for (int j = 0; j < NTOK; ++j) {
            float p = pi[j];
            uint2 vv = *(const uint2*)&sv[j * 64 + d4];
            float2 v01 = __half22float2(*(const __half2*)&vv.x);
            float2 v23 = __half22float2(*(const __half2*)&vv.y);
            a.x = fmaf(p, v01.x, a.x); a.y = fmaf(p, v01.y, a.y);
            a.z = fmaf(p, v23.x, a.z); a.w = fmaf(p, v23.y, a.w);
        }
        __half2 o0 = __floats2half2_rn(a.x, a.y);
        __half2 o1 = __floats2half2_rn(a.z, a.w);
        uint2 st;
        st.x = *(uint32_t*)&o0;
        st.y = *(uint32_t*)&o1;
        *(uint2*)&g_B[base + (size_t)i * DIMC + d4] = st;
    }
}

// ---------------- launch ----------------
extern "C" void kernel_launch(void* const* d_in, const int* in_sizes, int n_in,
                              void* d_out, int out_size) {
    const float* landmark = (const float*)d_in[0];
    const float* image    = (const float*)d_in[1];
    const float* Wq = (const float*)d_in[2];
    const float* bq = (const float*)d_in[3];
    const float* Wk = (const float*)d_in[4];
    const float* bk = (const float*)d_in[5];
    const float* Wv = (const float*)d_in[6];
    const float* bv = (const float*)d_in[7];
    const float* Wo = (const float*)d_in[8];
    const float* bo = (const float*)d_in[9];
    const float* bt = (const float*)d_in[10];
    const int*   ri = (const int*)d_in[11];
    float* out = (float*)d_out;

    cudaFuncSetAttribute(gemm_h, cudaFuncAttributeMaxDynamicSharedMemorySize, SMEMSZ);

    // fp32 -> fp16 conversions
    f2h<<<2048, 256>>>(landmark, 0, MROWS * DIMC);
    f2h<<<2048, 256>>>(image,    1, MROWS * DIMC);
    f2h<<<256, 256>>>(Wq, 2, DIMC * DIMC);
    f2h<<<256, 256>>>(Wk, 3, DIMC * DIMC);
    f2h<<<256, 256>>>(Wv, 4, DIMC * DIMC);
    f2h<<<256, 256>>>(Wo, 5, DIMC * DIMC);

    dim3 gg(DIMC / BN, MROWS / BM);   // (8, 392)
    gemm_h<<<gg, 256, SMEMSZ>>>(bq, nullptr, 0, 0, 1);  // Q = A @ Wq^T
    gemm_h<<<gg, 256, SMEMSZ>>>(bk, nullptr, 1, 1, 2);  // K = B @ Wk^T
    gemm_h<<<gg, 256, SMEMSZ>>>(bv, nullptr, 1, 2, 3);  // V = B @ Wv^T

    bias_gather<<<(NTOK * NTOK + 255) / 256, 256>>>(bt, ri);
    attn_kernel<<<dim3(BATCH, HEADS), 256>>>();          // -> g_B

    gemm_h<<<gg, 256, SMEMSZ>>>(bo, out, 1, 3, 0);       // out = attn @ Wo^T
}

// round 5
// speedup vs baseline: 1.7484x; 1.5833x over previous
#include <cuda_runtime.h>
#include <cuda_fp16.h>
#include <cstdint>

#define DIMC   1024
#define HEADS  16
#define NTOK   49
#define BATCH  1024
#define MROWS  (BATCH * NTOK)   // 50176
#define SCALE  0.125f

// ---------------- half scratch ----------------
__device__ __half g_A[(size_t)MROWS * DIMC];     // landmark half
__device__ __half g_B[(size_t)MROWS * DIMC];     // image half, later attn output
__device__ __half g_Q[(size_t)MROWS * DIMC];
__device__ __half g_K[(size_t)MROWS * DIMC];
__device__ __half g_V[(size_t)MROWS * DIMC];
__device__ __half g_Wh[4 * (size_t)DIMC * DIMC];
__device__ float  g_bias[HEADS * NTOK * NTOK];

// ---------------- conversions ----------------
__global__ void f2h_inputs(const float* __restrict__ a, const float* __restrict__ b) {
    const int n4 = MROWS * DIMC / 4;
    int i = blockIdx.x * blockDim.x + threadIdx.x;
    int stride = gridDim.x * blockDim.x;
    for (int t = i; t < n4; t += stride) {
        float4 v = ((const float4*)a)[t];
        __half2 h0 = __floats2half2_rn(v.x, v.y), h1 = __floats2half2_rn(v.z, v.w);
        ((uint2*)g_A)[t] = make_uint2(*(uint32_t*)&h0, *(uint32_t*)&h1);
        v = ((const float4*)b)[t];
        h0 = __floats2half2_rn(v.x, v.y); h1 = __floats2half2_rn(v.z, v.w);
        ((uint2*)g_B)[t] = make_uint2(*(uint32_t*)&h0, *(uint32_t*)&h1);
    }
}

__global__ void f2h_weights(const float* __restrict__ w0, const float* __restrict__ w1,
                            const float* __restrict__ w2, const float* __restrict__ w3) {
    const float* srcs[4] = {w0, w1, w2, w3};
    const int n4 = DIMC * DIMC / 4;
    int i = blockIdx.x * blockDim.x + threadIdx.x;
    int stride = gridDim.x * blockDim.x;
#pragma unroll
    for (int m = 0; m < 4; ++m) {
        const float4* src = (const float4*)srcs[m];
        uint2* dst = (uint2*)(g_Wh + (size_t)m * DIMC * DIMC);
        for (int t = i; t < n4; t += stride) {
            float4 v = src[t];
            __half2 h0 = __floats2half2_rn(v.x, v.y), h1 = __floats2half2_rn(v.z, v.w);
            dst[t] = make_uint2(*(uint32_t*)&h0, *(uint32_t*)&h1);
        }
    }
}

// ---------------- asm helpers ----------------
__device__ __forceinline__ void cp_async16(uint32_t saddr, const void* g) {
    asm volatile("cp.async.cg.shared.global [%0], [%1], 16;\n" :: "r"(saddr), "l"(g) : "memory");
}
__device__ __forceinline__ void cp_commit() { asm volatile("cp.async.commit_group;\n" ::: "memory"); }
__device__ __forceinline__ void cp_wait1() { asm volatile("cp.async.wait_group 1;\n" ::: "memory"); }

__device__ __forceinline__ void mma_f16(float c[4], uint32_t a0, uint32_t a1, uint32_t a2,
                                        uint32_t a3, uint32_t b0, uint32_t b1) {
    asm volatile(
        "mma.sync.aligned.m16n8k16.row.col.f32.f16.f16.f32 "
        "{%0,%1,%2,%3}, {%4,%5,%6,%7}, {%8,%9}, {%0,%1,%2,%3};\n"
        : "+f"(c[0]), "+f"(c[1]), "+f"(c[2]), "+f"(c[3])
        : "r"(a0), "r"(a1), "r"(a2), "r"(a3), "r"(b0), "r"(b1));
}

__device__ __forceinline__ void ldsm_x4(uint32_t& r0, uint32_t& r1, uint32_t& r2, uint32_t& r3,
                                        uint32_t addr) {
    asm volatile("ldmatrix.sync.aligned.m8n8.x4.shared.b16 {%0,%1,%2,%3}, [%4];"
                 : "=r"(r0), "=r"(r1), "=r"(r2), "=r"(r3) : "r"(addr));
}

// ---------------- FP16 GEMM: Y[M,1024] = X @ W^T + bias ----------------
#define BM 128
#define BN 128
#define BKH 64
#define NKT (DIMC / BKH)           // 16
#define TILE_A (BM * 128)          // 16384 B
#define SLOT (2 * TILE_A)
#define SMEMSZ (3 * SLOT)          // 98304 B

__global__ __launch_bounds__(256, 2) void gemm_h(
    const float* __restrict__ bias, float* __restrict__ Yf,
    int xsel, int wsel, int ysel)
{
    extern __shared__ __align__(128) uint8_t smem[];
    const __half* X = xsel ? g_B : g_A;
    const __half* W = g_Wh + (size_t)wsel * DIMC * DIMC;
    __half* Yh = (ysel == 1) ? g_Q : (ysel == 2) ? g_K : g_V;

    const int tid = threadIdx.x, wid = tid >> 5, lane = tid & 31;
    const int wm = wid >> 2, wn = wid & 3;
    const int m0 = blockIdx.y * BM, n0 = blockIdx.x * BN;
    const uint32_t sbase = (uint32_t)__cvta_generic_to_shared(smem);

    float acc[4][4][4];
#pragma unroll
    for (int a = 0; a < 4; ++a)
#pragma unroll
        for (int b = 0; b < 4; ++b)
#pragma unroll
            for (int c = 0; c < 4; ++c) acc[a][b][c] = 0.f;

    // ---- ldmatrix per-thread address components ----
    const int lane_r = lane & 15;          // A row within 16
    const int halfA  = lane >> 4;          // A granule half
    const int swA    = lane_r & 7;
    uint32_t offA[4];
#pragma unroll
    for (int mi = 0; mi < 4; ++mi)
        offA[mi] = (uint32_t)((wm * 64 + mi * 16 + lane_r) * 128);

    const int quad = lane >> 3;            // 0..3
    const int swB  = lane & 7;
    const int gselB = quad & 1;
    uint32_t offB[2];
#pragma unroll
    for (int pi = 0; pi < 2; ++pi)
        offB[pi] = (uint32_t)((wn * 32 + (2 * pi + (quad >> 1)) * 8 + (lane & 7)) * 128);

    // ---- stage loader ----
    const int row = tid >> 1;
    const int g0 = (tid & 1) * 4;
    const int swr = row & 7;
    auto load_stage = [&](int slot, int kt) {
        const __half* xa = X + (size_t)(m0 + row) * DIMC + kt * BKH;
        const __half* xb = W + (size_t)(n0 + row) * DIMC + kt * BKH;
        uint32_t sa = sbase + slot * SLOT + row * 128;
        uint32_t sb = sa + TILE_A;
#pragma unroll
        for (int q = 0; q < 4; ++q) {
            int g = g0 + q;
            uint32_t off = (uint32_t)((g ^ swr) << 4);
            cp_async16(sa + off, xa + g * 8);
            cp_async16(sb + off, xb + g * 8);
        }
        cp_commit();
    };

    load_stage(0, 0);
    load_stage(1, 1);

    const int r8 = lane >> 2, cp2 = (lane & 3) * 2;

    for (int kt = 0; kt < NKT; ++kt) {
        cp_wait1();
        __syncthreads();
        if (kt + 2 < NKT) load_stage((kt + 2) % 3, kt + 2);

        const uint32_t baseA = sbase + (kt % 3) * SLOT;
        const uint32_t baseB = baseA + TILE_A;
#pragma unroll
        for (int ks = 0; ks < 4; ++ks) {
            uint32_t a[4][4], b[2][4];
            const uint32_t gA = (uint32_t)(((ks * 2 + halfA) ^ swA) << 4);
            const uint32_t gB = (uint32_t)(((ks * 2 + gselB) ^ swB) << 4);
#pragma unroll
            for (int mi = 0; mi < 4; ++mi)
                ldsm_x4(a[mi][0], a[mi][1], a[mi][2], a[mi][3], baseA + offA[mi] + gA);
#pragma unroll
            for (int pi = 0; pi < 2; ++pi)
                ldsm_x4(b[pi][0], b[pi][1], b[pi][2], b[pi][3], baseB + offB[pi] + gB);
#pragma unroll
            for (int mi = 0; mi < 4; ++mi) {
                mma_f16(acc[mi][0], a[mi][0], a[mi][1], a[mi][2], a[mi][3], b[0][0], b[0][1]);
                mma_f16(acc[mi][1], a[mi][0], a[mi][1], a[mi][2], a[mi][3], b[0][2], b[0][3]);
                mma_f16(acc[mi][2], a[mi][0], a[mi][1], a[mi][2], a[mi][3], b[1][0], b[1][1]);
                mma_f16(acc[mi][3], a[mi][0], a[mi][1], a[mi][2], a[mi][3], b[1][2], b[1][3]);
            }
        }
        __syncthreads();
    }

    // epilogue
#pragma unroll
    for (int mi = 0; mi < 4; ++mi) {
        int r = m0 + wm * 64 + mi * 16 + r8;
#pragma unroll
        for (int ni = 0; ni < 4; ++ni) {
            int cc = n0 + wn * 32 + ni * 8 + cp2;
            float b0 = bias[cc], b1 = bias[cc + 1];
            float v0 = acc[mi][ni][0] + b0, v1 = acc[mi][ni][1] + b1;
            float v2 = acc[mi][ni][2] + b0, v3 = acc[mi][ni][3] + b1;
            if (ysel == 0) {
                *(float2*)&Yf[(size_t)r * DIMC + cc]       = make_float2(v0, v1);
                *(float2*)&Yf[(size_t)(r + 8) * DIMC + cc] = make_float2(v2, v3);
            } else {
                __half2 h0 = __floats2half2_rn(v0, v1);
                __half2 h1 = __floats2half2_rn(v2, v3);
                *(__half2*)&Yh[(size_t)r * DIMC + cc]       = h0;
                *(__half2*)&Yh[(size_t)(r + 8) * DIMC + cc] = h1;
            }
        }
    }
}

// ---------------- bias precompute ----------------
__global__ void bias_gather(const float* __restrict__ bt, const int* __restrict__ ri) {
    int t = blockIdx.x * 256 + threadIdx.x;
    if (t < NTOK * NTOK) {
        int idx = ri[t] * HEADS;
#pragma unroll
        for (int h = 0; h < HEADS; ++h)
            g_bias[h * (NTOK * NTOK) + t] = bt[idx + h];
    }
}

// ---------------- fused windowed attention per (b,h) ----------------
__global__ __launch_bounds__(256) void attn_kernel() {
    __shared__ __half   sq[NTOK * 64];
    __shared__ __half2  skT[32 * 56];
    __shared__ __half   sv[NTOK * 64];
    __shared__ float    sp[NTOK * NTOK];

    const int b = blockIdx.x, h = blockIdx.y;
    const int tid = threadIdx.x, warp = tid >> 5, lane = tid & 31;
    const size_t base = (size_t)(b * NTOK) * DIMC + h * 64;

    for (int t = tid; t < NTOK * 8; t += 256) {
        int row = t >> 3, g = t & 7;
        *(uint4*)&sq[row * 64 + g * 8] = *(const uint4*)&g_Q[base + (size_t)row * DIMC + g * 8];
        *(uint4*)&sv[row * 64 + g * 8] = *(const uint4*)&g_V[base + (size_t)row * DIMC + g * 8];
        uint4 kk = *(const uint4*)&g_K[base + (size_t)row * DIMC + g * 8];
        const __half2* kp = (const __half2*)&kk;
#pragma unroll
        for (int w = 0; w < 4; ++w) skT[(g * 4 + w) * 56 + row] = kp[w];
    }
    const float* gb = &g_bias[h * (NTOK * NTOK)];
    for (int t = tid; t < NTOK * NTOK; t += 256) sp[t] = gb[t];
    __syncthreads();

    for (int i = warp; i < NTOK; i += 8) {
        const __half2* qp = (const __half2*)&sq[i * 64];
        int j1 = lane, j2 = lane + 32;
        bool has2 = (j2 < NTOK);
        int j2c = has2 ? j2 : 0;
        float s1 = 0.f, s2 = 0.f;
#pragma unroll
        for (int d2 = 0; d2 < 32; ++d2) {
            float2 q  = __half22float2(qp[d2]);
            float2 k1 = __half22float2(skT[d2 * 56 + j1]);
            float2 k2 = __half22float2(skT[d2 * 56 + j2c]);
            s1 = fmaf(q.x, k1.x, fmaf(q.y, k1.y, s1));
            s2 = fmaf(q.x, k2.x, fmaf(q.y, k2.y, s2));
        }
        s1 = s1 * SCALE + sp[i * NTOK + j1];
        float s2v = has2 ? (s2 * SCALE + sp[i * NTOK + j2]) : -1e30f;

        float m = fmaxf(s1, s2v);
#pragma unroll
        for (int o = 16; o > 0; o >>= 1) m = fmaxf(m, __shfl_xor_sync(0xFFFFFFFFu, m, o));
        float e1 = __expf(s1 - m);
        float e2 = has2 ? __expf(s2v - m) : 0.f;
        float sum = e1 + e2;
#pragma unroll
        for (int o = 16; o > 0; o >>= 1) sum += __shfl_xor_sync(0xFFFFFFFFu, sum, o);
        float inv = 1.f / sum;
        sp[i * NTOK + j1] = e1 * inv;
        if (has2) sp[i * NTOK + j2] = e2 * inv;
    }
    __syncthreads();

    for (int t = tid; t < NTOK * 16; t += 256) {
        int i = t >> 4, d4 = (t & 15) * 4;
        const float* pi = &sp[i * NTOK];
        float4 a = make_float4(0.f, 0.f, 0.f, 0.f);
#pragma unroll 7
        for (int j = 0; j < NTOK; ++j) {
            float p = pi[j];
            uint2 vv = *(const uint2*)&sv[j * 64 + d4];
            float2 v01 = __half22float2(*(const __half2*)&vv.x);
            float2 v23 = __half22float2(*(const __half2*)&vv.y);
            a.x = fmaf(p, v01.x, a.x); a.y = fmaf(p, v01.y, a.y);
            a.z = fmaf(p, v23.x, a.z); a.w = fmaf(p, v23.y, a.w);
        }
        __half2 o0 = __floats2half2_rn(a.x, a.y);
        __half2 o1 = __floats2half2_rn(a.z, a.w);
        *(uint2*)&g_B[base + (size_t)i * DIMC + d4] =
            make_uint2(*(uint32_t*)&o0, *(uint32_t*)&o1);
    }
}

// ---------------- launch ----------------
extern "C" void kernel_launch(void* const* d_in, const int* in_sizes, int n_in,
                              void* d_out, int out_size) {
    const float* landmark = (const float*)d_in[0];
    const float* image    = (const float*)d_in[1];
    const float* Wq = (const float*)d_in[2];
    const float* bq = (const float*)d_in[3];
    const float* Wk = (const float*)d_in[4];
    const float* bk = (const float*)d_in[5];
    const float* Wv = (const float*)d_in[6];
    const float* bv = (const float*)d_in[7];
    const float* Wo = (const float*)d_in[8];
    const float* bo = (const float*)d_in[9];
    const float* bt = (const float*)d_in[10];
    const int*   ri = (const int*)d_in[11];
    float* out = (float*)d_out;

    cudaFuncSetAttribute(gemm_h, cudaFuncAttributeMaxDynamicSharedMemorySize, SMEMSZ);

    dim3 gg(DIMC / BN, MROWS / BM);   // (8, 392)

    bias_gather<<<(NTOK * NTOK + 255) / 256, 256>>>(bt, ri);         // 0
    f2h_inputs<<<4096, 256>>>(landmark, image);                      // 1
    f2h_weights<<<512, 256>>>(Wq, Wk, Wv, Wo);                       // 2
    gemm_h<<<gg, 256, SMEMSZ>>>(bq, nullptr, 0, 0, 1);               // 3: Q
    gemm_h<<<gg, 256, SMEMSZ>>>(bk, nullptr, 1, 1, 2);               // 4: K
    gemm_h<<<gg, 256, SMEMSZ>>>(bv, nullptr, 1, 2, 3);               // 5: V  (ncu -s 5 target)
    attn_kernel<<<dim3(BATCH, HEADS), 256>>>();                      // 6
    gemm_h<<<gg, 256, SMEMSZ>>>(bo, out, 1, 3, 0);                   // 7: O
}

// round 6
// speedup vs baseline: 1.7592x; 1.0061x over previous
#include <cuda_runtime.h>
#include <cuda_fp16.h>
#include <cstdint>

#define DIMC   1024
#define HEADS  16
#define NTOK   49
#define BATCH  1024
#define MROWS  (BATCH * NTOK)   // 50176
#define SCALE  0.125f

// ---------------- half scratch ----------------
__device__ __half g_A[(size_t)MROWS * DIMC];     // landmark half
__device__ __half g_B[(size_t)MROWS * DIMC];     // image half, later attn output
__device__ __half g_Q[(size_t)MROWS * DIMC];
__device__ __half g_K[(size_t)MROWS * DIMC];
__device__ __half g_V[(size_t)MROWS * DIMC];
__device__ __half g_Wh[4 * (size_t)DIMC * DIMC];
__device__ float  g_bias[HEADS * NTOK * NTOK];

// ---------------- conversions ----------------
__global__ void f2h_inputs(const float* __restrict__ a, const float* __restrict__ b) {
    const int n4 = MROWS * DIMC / 4;
    int i = blockIdx.x * blockDim.x + threadIdx.x;
    int stride = gridDim.x * blockDim.x;
    for (int t = i; t < n4; t += stride) {
        float4 v = ((const float4*)a)[t];
        __half2 h0 = __floats2half2_rn(v.x, v.y), h1 = __floats2half2_rn(v.z, v.w);
        ((uint2*)g_A)[t] = make_uint2(*(uint32_t*)&h0, *(uint32_t*)&h1);
        v = ((const float4*)b)[t];
        h0 = __floats2half2_rn(v.x, v.y); h1 = __floats2half2_rn(v.z, v.w);
        ((uint2*)g_B)[t] = make_uint2(*(uint32_t*)&h0, *(uint32_t*)&h1);
    }
}

// weights fp32->fp16 + bias-table gather, one kernel
__global__ void f2h_weights_bias(const float* __restrict__ w0, const float* __restrict__ w1,
                                 const float* __restrict__ w2, const float* __restrict__ w3,
                                 const float* __restrict__ bt, const int* __restrict__ ri) {
    const float* srcs[4] = {w0, w1, w2, w3};
    const int n4 = DIMC * DIMC / 4;
    int i = blockIdx.x * blockDim.x + threadIdx.x;
    int stride = gridDim.x * blockDim.x;
#pragma unroll
    for (int m = 0; m < 4; ++m) {
        const float4* src = (const float4*)srcs[m];
        uint2* dst = (uint2*)(g_Wh + (size_t)m * DIMC * DIMC);
        for (int t = i; t < n4; t += stride) {
            float4 v = src[t];
            __half2 h0 = __floats2half2_rn(v.x, v.y), h1 = __floats2half2_rn(v.z, v.w);
            dst[t] = make_uint2(*(uint32_t*)&h0, *(uint32_t*)&h1);
        }
    }
    for (int t = i; t < NTOK * NTOK; t += stride) {
        int idx = ri[t] * HEADS;
#pragma unroll
        for (int h = 0; h < HEADS; ++h)
            g_bias[h * (NTOK * NTOK) + t] = bt[idx + h];
    }
}

// ---------------- asm helpers ----------------
__device__ __forceinline__ void cp_async16(uint32_t saddr, const void* g) {
    asm volatile("cp.async.cg.shared.global [%0], [%1], 16;\n" :: "r"(saddr), "l"(g) : "memory");
}
__device__ __forceinline__ void cp_commit() { asm volatile("cp.async.commit_group;\n" ::: "memory"); }
__device__ __forceinline__ void cp_wait1() { asm volatile("cp.async.wait_group 1;\n" ::: "memory"); }

__device__ __forceinline__ void mma_f16(float c[4], uint32_t a0, uint32_t a1, uint32_t a2,
                                        uint32_t a3, uint32_t b0, uint32_t b1) {
    asm volatile(
        "mma.sync.aligned.m16n8k16.row.col.f32.f16.f16.f32 "
        "{%0,%1,%2,%3}, {%4,%5,%6,%7}, {%8,%9}, {%0,%1,%2,%3};\n"
        : "+f"(c[0]), "+f"(c[1]), "+f"(c[2]), "+f"(c[3])
        : "r"(a0), "r"(a1), "r"(a2), "r"(a3), "r"(b0), "r"(b1));
}

__device__ __forceinline__ void ldsm_x4(uint32_t& r0, uint32_t& r1, uint32_t& r2, uint32_t& r3,
                                        uint32_t addr) {
    asm volatile("ldmatrix.sync.aligned.m8n8.x4.shared.b16 {%0,%1,%2,%3}, [%4];"
                 : "=r"(r0), "=r"(r1), "=r"(r2), "=r"(r3) : "r"(addr));
}

// ---------------- FP16 GEMM: Y[M,1024] = X @ W^T + bias ----------------
#define BM 128
#define BN 128
#define BKH 64
#define NKT (DIMC / BKH)           // 16
#define TILE_A (BM * 128)          // 16384 B
#define SLOT (2 * TILE_A)
#define SMEMSZ (3 * SLOT)          // 98304 B

__global__ __launch_bounds__(256, 2) void gemm_h(
    const float* __restrict__ bias, float* __restrict__ Yf,
    int xsel, int wsel, int ysel)
{
    extern __shared__ __align__(128) uint8_t smem[];
    const __half* X = xsel ? g_B : g_A;
    const __half* W = g_Wh + (size_t)wsel * DIMC * DIMC;
    __half* Yh = (ysel == 1) ? g_Q : (ysel == 2) ? g_K : g_V;

    const int tid = threadIdx.x, wid = tid >> 5, lane = tid & 31;
    const int wm = wid >> 2, wn = wid & 3;
    const int m0 = blockIdx.y * BM, n0 = blockIdx.x * BN;
    const uint32_t sbase = (uint32_t)__cvta_generic_to_shared(smem);

    float acc[4][4][4];
#pragma unroll
    for (int a = 0; a < 4; ++a)
#pragma unroll
        for (int b = 0; b < 4; ++b)
#pragma unroll
            for (int c = 0; c < 4; ++c) acc[a][b][c] = 0.f;

    // ldmatrix per-thread addresses
    const int lane_r = lane & 15;
    const int halfA  = lane >> 4;
    const int swA    = lane_r & 7;
    uint32_t offA[4];
#pragma unroll
    for (int mi = 0; mi < 4; ++mi)
        offA[mi] = (uint32_t)((wm * 64 + mi * 16 + lane_r) * 128);

    const int quad = lane >> 3;
    const int swB  = lane & 7;
    const int gselB = quad & 1;
    uint32_t offB[2];
#pragma unroll
    for (int pi = 0; pi < 2; ++pi)
        offB[pi] = (uint32_t)((wn * 32 + (2 * pi + (quad >> 1)) * 8 + (lane & 7)) * 128);

    // stage loader
    const int row = tid >> 1;
    const int g0 = (tid & 1) * 4;
    const int swr = row & 7;
    auto load_stage = [&](int slot, int kt) {
        const __half* xa = X + (size_t)(m0 + row) * DIMC + kt * BKH;
        const __half* xb = W + (size_t)(n0 + row) * DIMC + kt * BKH;
        uint32_t sa = sbase + slot * SLOT + row * 128;
        uint32_t sb = sa + TILE_A;
#pragma unroll
        for (int q = 0; q < 4; ++q) {
            int g = g0 + q;
            uint32_t off = (uint32_t)((g ^ swr) << 4);
            cp_async16(sa + off, xa + g * 8);
            cp_async16(sb + off, xb + g * 8);
        }
        cp_commit();
    };

    load_stage(0, 0);
    load_stage(1, 1);

    const int r8 = lane >> 2, cp2 = (lane & 3) * 2;

    for (int kt = 0; kt < NKT; ++kt) {
        cp_wait1();
        __syncthreads();           // single barrier per iteration (safe with 3 stages)
        if (kt + 2 < NKT) load_stage((kt + 2) % 3, kt + 2);

        const uint32_t baseA = sbase + (kt % 3) * SLOT;
        const uint32_t baseB = baseA + TILE_A;
#pragma unroll
        for (int ks = 0; ks < 4; ++ks) {
            uint32_t a[4][4], b[2][4];
            const uint32_t gA = (uint32_t)(((ks * 2 + halfA) ^ swA) << 4);
            const uint32_t gB = (uint32_t)(((ks * 2 + gselB) ^ swB) << 4);
#pragma unroll
            for (int mi = 0; mi < 4; ++mi)
                ldsm_x4(a[mi][0], a[mi][1], a[mi][2], a[mi][3], baseA + offA[mi] + gA);
#pragma unroll
            for (int pi = 0; pi < 2; ++pi)
                ldsm_x4(b[pi][0], b[pi][1], b[pi][2], b[pi][3], baseB + offB[pi] + gB);
#pragma unroll
            for (int mi = 0; mi < 4; ++mi) {
                mma_f16(acc[mi][0], a[mi][0], a[mi][1], a[mi][2], a[mi][3], b[0][0], b[0][1]);
                mma_f16(acc[mi][1], a[mi][0], a[mi][1], a[mi][2], a[mi][3], b[0][2], b[0][3]);
                mma_f16(acc[mi][2], a[mi][0], a[mi][1], a[mi][2], a[mi][3], b[1][0], b[1][1]);
                mma_f16(acc[mi][3], a[mi][0], a[mi][1], a[mi][2], a[mi][3], b[1][2], b[1][3]);
            }
        }
    }

    // epilogue
#pragma unroll
    for (int mi = 0; mi < 4; ++mi) {
        int r = m0 + wm * 64 + mi * 16 + r8;
#pragma unroll
        for (int ni = 0; ni < 4; ++ni) {
            int cc = n0 + wn * 32 + ni * 8 + cp2;
            float b0 = bias[cc], b1 = bias[cc + 1];
            float v0 = acc[mi][ni][0] + b0, v1 = acc[mi][ni][1] + b1;
            float v2 = acc[mi][ni][2] + b0, v3 = acc[mi][ni][3] + b1;
            if (ysel == 0) {
                *(float2*)&Yf[(size_t)r * DIMC + cc]       = make_float2(v0, v1);
                *(float2*)&Yf[(size_t)(r + 8) * DIMC + cc] = make_float2(v2, v3);
            } else {
                __half2 h0 = __floats2half2_rn(v0, v1);
                __half2 h1 = __floats2half2_rn(v2, v3);
                *(__half2*)&Yh[(size_t)r * DIMC + cc]       = h0;
                *(__half2*)&Yh[(size_t)(r + 8) * DIMC + cc] = h1;
            }
        }
    }
}

// ---------------- fused windowed attention per (b,h) ----------------
__global__ __launch_bounds__(256) void attn_kernel() {
    __shared__ __half   sq[NTOK * 64];
    __shared__ __half2  skT[32 * 56];
    __shared__ __half   sv[NTOK * 64];
    __shared__ float    sp[NTOK * NTOK];

    const int b = blockIdx.x, h = blockIdx.y;
    const int tid = threadIdx.x, warp = tid >> 5, lane = tid & 31;
    const size_t base = (size_t)(b * NTOK) * DIMC + h * 64;

    for (int t = tid; t < NTOK * 8; t += 256) {
        int row = t >> 3, g = t & 7;
        *(uint4*)&sq[row * 64 + g * 8] = *(const uint4*)&g_Q[base + (size_t)row * DIMC + g * 8];
        *(uint4*)&sv[row * 64 + g * 8] = *(const uint4*)&g_V[base + (size_t)row * DIMC + g * 8];
        uint4 kk = *(const uint4*)&g_K[base + (size_t)row * DIMC + g * 8];
        const __half2* kp = (const __half2*)&kk;
#pragma unroll
        for (int w = 0; w < 4; ++w) skT[(g * 4 + w) * 56 + row] = kp[w];
    }
    const float* gb = &g_bias[h * (NTOK * NTOK)];
    for (int t = tid; t < NTOK * NTOK; t += 256) sp[t] = gb[t];
    __syncthreads();

    for (int i = warp; i < NTOK; i += 8) {
        const __half2* qp = (const __half2*)&sq[i * 64];
        int j1 = lane, j2 = lane + 32;
        bool has2 = (j2 < NTOK);
        int j2c = has2 ? j2 : 0;
        float s1 = 0.f, s2 = 0.f;
#pragma unroll
        for (int d2 = 0; d2 < 32; ++d2) {
            float2 q  = __half22float2(qp[d2]);
            float2 k1 = __half22float2(skT[d2 * 56 + j1]);
            float2 k2 = __half22float2(skT[d2 * 56 + j2c]);
            s1 = fmaf(q.x, k1.x, fmaf(q.y, k1.y, s1));
            s2 = fmaf(q.x, k2.x, fmaf(q.y, k2.y, s2));
        }
        s1 = s1 * SCALE + sp[i * NTOK + j1];
        float s2v = has2 ? (s2 * SCALE + sp[i * NTOK + j2]) : -1e30f;

        float m = fmaxf(s1, s2v);
#pragma unroll
        for (int o = 16; o > 0; o >>= 1) m = fmaxf(m, __shfl_xor_sync(0xFFFFFFFFu, m, o));
        float e1 = __expf(s1 - m);
        float e2 = has2 ? __expf(s2v - m) : 0.f;
        float sum = e1 + e2;
#pragma unroll
        for (int o = 16; o > 0; o >>= 1) sum += __shfl_xor_sync(0xFFFFFFFFu, sum, o);
        float inv = 1.f / sum;
        sp[i * NTOK + j1] = e1 * inv;
        if (has2) sp[i * NTOK + j2] = e2 * inv;
    }
    __syncthreads();

    for (int t = tid; t < NTOK * 16; t += 256) {
        int i = t >> 4, d4 = (t & 15) * 4;
        const float* pi = &sp[i * NTOK];
        float4 a = make_float4(0.f, 0.f, 0.f, 0.f);
#pragma unroll 7
        for (int j = 0; j < NTOK; ++j) {
            float p = pi[j];
            uint2 vv = *(const uint2*)&sv[j * 64 + d4];
            float2 v01 = __half22float2(*(const __half2*)&vv.x);
            float2 v23 = __half22float2(*(const __half2*)&vv.y);
            a.x = fmaf(p, v01.x, a.x); a.y = fmaf(p, v01.y, a.y);
            a.z = fmaf(p, v23.x, a.z); a.w = fmaf(p, v23.y, a.w);
        }
        __half2 o0 = __floats2half2_rn(a.x, a.y);
        __half2 o1 = __floats2half2_rn(a.z, a.w);
        *(uint2*)&g_B[base + (size_t)i * DIMC + d4] =
            make_uint2(*(uint32_t*)&o0, *(uint32_t*)&o1);
    }
}

// ---------------- launch ----------------
extern "C" void kernel_launch(void* const* d_in, const int* in_sizes, int n_in,
                              void* d_out, int out_size) {
    const float* landmark = (const float*)d_in[0];
    const float* image    = (const float*)d_in[1];
    const float* Wq = (const float*)d_in[2];
    const float* bq = (const float*)d_in[3];
    const float* Wk = (const float*)d_in[4];
    const float* bk = (const float*)d_in[5];
    const float* Wv = (const float*)d_in[6];
    const float* bv = (const float*)d_in[7];
    const float* Wo = (const float*)d_in[8];
    const float* bo = (const float*)d_in[9];
    const float* bt = (const float*)d_in[10];
    const int*   ri = (const int*)d_in[11];
    float* out = (float*)d_out;

    cudaFuncSetAttribute(gemm_h, cudaFuncAttributeMaxDynamicSharedMemorySize, SMEMSZ);

    dim3 gg(DIMC / BN, MROWS / BM);   // (8, 392)

    f2h_inputs<<<8192, 256>>>(landmark, image);                      // 0
    f2h_weights_bias<<<512, 256>>>(Wq, Wk, Wv, Wo, bt, ri);          // 1
    gemm_h<<<gg, 256, SMEMSZ>>>(bq, nullptr, 0, 0, 1);               // 2: Q
    gemm_h<<<gg, 256, SMEMSZ>>>(bk, nullptr, 1, 1, 2);               // 3: K
    gemm_h<<<gg, 256, SMEMSZ>>>(bv, nullptr, 1, 2, 3);               // 4: V
    attn_kernel<<<dim3(BATCH, HEADS), 256>>>();                      // 5: attn (ncu -s 5)
    gemm_h<<<gg, 256, SMEMSZ>>>(bo, out, 1, 3, 0);                   // 6: O
}

// round 7
// speedup vs baseline: 2.4820x; 1.4109x over previous
#include <cuda_runtime.h>
#include <cuda_fp16.h>
#include <cstdint>

#define DIMC   1024
#define HEADS  16
#define NTOK   49
#define BATCH  1024
#define MROWS  (BATCH * NTOK)   // 50176
#define SCALE  0.125f

// ---------------- half scratch ----------------
__device__ __half g_A[(size_t)MROWS * DIMC];
__device__ __half g_B[(size_t)MROWS * DIMC];
__device__ __half g_Q[(size_t)MROWS * DIMC];
__device__ __half g_K[(size_t)MROWS * DIMC];
__device__ __half g_V[(size_t)MROWS * DIMC];
__device__ __half g_Wh[4 * (size_t)DIMC * DIMC];
__device__ float  g_bias[HEADS * NTOK * NTOK];

// ---------------- conversions ----------------
__global__ void f2h_inputs(const float* __restrict__ a, const float* __restrict__ b) {
    const int n4 = MROWS * DIMC / 4;
    int i = blockIdx.x * blockDim.x + threadIdx.x;
    int stride = gridDim.x * blockDim.x;
    for (int t = i; t < n4; t += stride) {
        float4 v = ((const float4*)a)[t];
        __half2 h0 = __floats2half2_rn(v.x, v.y), h1 = __floats2half2_rn(v.z, v.w);
        ((uint2*)g_A)[t] = make_uint2(*(uint32_t*)&h0, *(uint32_t*)&h1);
        v = ((const float4*)b)[t];
        h0 = __floats2half2_rn(v.x, v.y); h1 = __floats2half2_rn(v.z, v.w);
        ((uint2*)g_B)[t] = make_uint2(*(uint32_t*)&h0, *(uint32_t*)&h1);
    }
}

__global__ void f2h_weights_bias(const float* __restrict__ w0, const float* __restrict__ w1,
                                 const float* __restrict__ w2, const float* __restrict__ w3,
                                 const float* __restrict__ bt, const int* __restrict__ ri) {
    const float* srcs[4] = {w0, w1, w2, w3};
    const int n4 = DIMC * DIMC / 4;
    int i = blockIdx.x * blockDim.x + threadIdx.x;
    int stride = gridDim.x * blockDim.x;
#pragma unroll
    for (int m = 0; m < 4; ++m) {
        const float4* src = (const float4*)srcs[m];
        uint2* dst = (uint2*)(g_Wh + (size_t)m * DIMC * DIMC);
        for (int t = i; t < n4; t += stride) {
            float4 v = src[t];
            __half2 h0 = __floats2half2_rn(v.x, v.y), h1 = __floats2half2_rn(v.z, v.w);
            dst[t] = make_uint2(*(uint32_t*)&h0, *(uint32_t*)&h1);
        }
    }
    for (int t = i; t < NTOK * NTOK; t += stride) {
        int idx = ri[t] * HEADS;
#pragma unroll
        for (int h = 0; h < HEADS; ++h)
            g_bias[h * (NTOK * NTOK) + t] = bt[idx + h];
    }
}

// ---------------- asm helpers ----------------
__device__ __forceinline__ void cp_async16(uint32_t saddr, const void* g) {
    asm volatile("cp.async.cg.shared.global [%0], [%1], 16;\n" :: "r"(saddr), "l"(g) : "memory");
}
__device__ __forceinline__ void cp_commit() { asm volatile("cp.async.commit_group;\n" ::: "memory"); }
__device__ __forceinline__ void cp_wait1() { asm volatile("cp.async.wait_group 1;\n" ::: "memory"); }

__device__ __forceinline__ void mma_f16(float c[4], uint32_t a0, uint32_t a1, uint32_t a2,
                                        uint32_t a3, uint32_t b0, uint32_t b1) {
    asm volatile(
        "mma.sync.aligned.m16n8k16.row.col.f32.f16.f16.f32 "
        "{%0,%1,%2,%3}, {%4,%5,%6,%7}, {%8,%9}, {%0,%1,%2,%3};\n"
        : "+f"(c[0]), "+f"(c[1]), "+f"(c[2]), "+f"(c[3])
        : "r"(a0), "r"(a1), "r"(a2), "r"(a3), "r"(b0), "r"(b1));
}

__device__ __forceinline__ void ldsm_x4(uint32_t& r0, uint32_t& r1, uint32_t& r2, uint32_t& r3,
                                        uint32_t addr) {
    asm volatile("ldmatrix.sync.aligned.m8n8.x4.shared.b16 {%0,%1,%2,%3}, [%4];"
                 : "=r"(r0), "=r"(r1), "=r"(r2), "=r"(r3) : "r"(addr));
}
__device__ __forceinline__ void ldsm_x4_t(uint32_t& r0, uint32_t& r1, uint32_t& r2, uint32_t& r3,
                                          uint32_t addr) {
    asm volatile("ldmatrix.sync.aligned.m8n8.x4.trans.shared.b16 {%0,%1,%2,%3}, [%4];"
                 : "=r"(r0), "=r"(r1), "=r"(r2), "=r"(r3) : "r"(addr));
}

// ---------------- FP16 GEMM (unchanged from round 5/6) ----------------
#define BM 128
#define BN 128
#define BKH 64
#define NKT (DIMC / BKH)
#define TILE_A (BM * 128)
#define SLOT (2 * TILE_A)
#define SMEMSZ (3 * SLOT)

__global__ __launch_bounds__(256, 2) void gemm_h(
    const float* __restrict__ bias, float* __restrict__ Yf,
    int xsel, int wsel, int ysel)
{
    extern __shared__ __align__(128) uint8_t smem[];
    const __half* X = xsel ? g_B : g_A;
    const __half* W = g_Wh + (size_t)wsel * DIMC * DIMC;
    __half* Yh = (ysel == 1) ? g_Q : (ysel == 2) ? g_K : g_V;

    const int tid = threadIdx.x, wid = tid >> 5, lane = tid & 31;
    const int wm = wid >> 2, wn = wid & 3;
    const int m0 = blockIdx.y * BM, n0 = blockIdx.x * BN;
    const uint32_t sbase = (uint32_t)__cvta_generic_to_shared(smem);

    float acc[4][4][4];
#pragma unroll
    for (int a = 0; a < 4; ++a)
#pragma unroll
        for (int b = 0; b < 4; ++b)
#pragma unroll
            for (int c = 0; c < 4; ++c) acc[a][b][c] = 0.f;

    const int lane_r = lane & 15;
    const int halfA  = lane >> 4;
    const int swA    = lane_r & 7;
    uint32_t offA[4];
#pragma unroll
    for (int mi = 0; mi < 4; ++mi)
        offA[mi] = (uint32_t)((wm * 64 + mi * 16 + lane_r) * 128);

    const int quad = lane >> 3;
    const int swB  = lane & 7;
    const int gselB = quad & 1;
    uint32_t offB[2];
#pragma unroll
    for (int pi = 0; pi < 2; ++pi)
        offB[pi] = (uint32_t)((wn * 32 + (2 * pi + (quad >> 1)) * 8 + (lane & 7)) * 128);

    const int row = tid >> 1;
    const int g0 = (tid & 1) * 4;
    const int swr = row & 7;
    auto load_stage = [&](int slot, int kt) {
        const __half* xa = X + (size_t)(m0 + row) * DIMC + kt * BKH;
        const __half* xb = W + (size_t)(n0 + row) * DIMC + kt * BKH;
        uint32_t sa = sbase + slot * SLOT + row * 128;
        uint32_t sb = sa + TILE_A;
#pragma unroll
        for (int q = 0; q < 4; ++q) {
            int g = g0 + q;
            uint32_t off = (uint32_t)((g ^ swr) << 4);
            cp_async16(sa + off, xa + g * 8);
            cp_async16(sb + off, xb + g * 8);
        }
        cp_commit();
    };

    load_stage(0, 0);
    load_stage(1, 1);

    const int r8 = lane >> 2, cp2 = (lane & 3) * 2;

    for (int kt = 0; kt < NKT; ++kt) {
        cp_wait1();
        __syncthreads();
        if (kt + 2 < NKT) load_stage((kt + 2) % 3, kt + 2);

        const uint32_t baseA = sbase + (kt % 3) * SLOT;
        const uint32_t baseB = baseA + TILE_A;
#pragma unroll
        for (int ks = 0; ks < 4; ++ks) {
            uint32_t a[4][4], b[2][4];
            const uint32_t gA = (uint32_t)(((ks * 2 + halfA) ^ swA) << 4);
            const uint32_t gB = (uint32_t)(((ks * 2 + gselB) ^ swB) << 4);
#pragma unroll
            for (int mi = 0; mi < 4; ++mi)
                ldsm_x4(a[mi][0], a[mi][1], a[mi][2], a[mi][3], baseA + offA[mi] + gA);
#pragma unroll
            for (int pi = 0; pi < 2; ++pi)
                ldsm_x4(b[pi][0], b[pi][1], b[pi][2], b[pi][3], baseB + offB[pi] + gB);
#pragma unroll
            for (int mi = 0; mi < 4; ++mi) {
                mma_f16(acc[mi][0], a[mi][0], a[mi][1], a[mi][2], a[mi][3], b[0][0], b[0][1]);
                mma_f16(acc[mi][1], a[mi][0], a[mi][1], a[mi][2], a[mi][3], b[0][2], b[0][3]);
                mma_f16(acc[mi][2], a[mi][0], a[mi][1], a[mi][2], a[mi][3], b[1][0], b[1][1]);
                mma_f16(acc[mi][3], a[mi][0], a[mi][1], a[mi][2], a[mi][3], b[1][2], b[1][3]);
            }
        }
    }

#pragma unroll
    for (int mi = 0; mi < 4; ++mi) {
        int r = m0 + wm * 64 + mi * 16 + r8;
#pragma unroll
        for (int ni = 0; ni < 4; ++ni) {
            int cc = n0 + wn * 32 + ni * 8 + cp2;
            float b0 = bias[cc], b1 = bias[cc + 1];
            float v0 = acc[mi][ni][0] + b0, v1 = acc[mi][ni][1] + b1;
            float v2 = acc[mi][ni][2] + b0, v3 = acc[mi][ni][3] + b1;
            if (ysel == 0) {
                *(float2*)&Yf[(size_t)r * DIMC + cc]       = make_float2(v0, v1);
                *(float2*)&Yf[(size_t)(r + 8) * DIMC + cc] = make_float2(v2, v3);
            } else {
                __half2 h0 = __floats2half2_rn(v0, v1);
                __half2 h1 = __floats2half2_rn(v2, v3);
                *(__half2*)&Yh[(size_t)r * DIMC + cc]       = h0;
                *(__half2*)&Yh[(size_t)(r + 8) * DIMC + cc] = h1;
            }
        }
    }
}

// ---------------- tensor-core windowed attention: one (b,h) per CTA ----------------
__global__ __launch_bounds__(128) void attn_mma() {
    __shared__ __align__(128) uint8_t sQ[64 * 128];   // Q tile; becomes P (half) after softmax
    __shared__ __align__(128) uint8_t sK[64 * 128];
    __shared__ __align__(128) uint8_t sV[64 * 128];
    __shared__ float sS[64 * 66];                     // fp32 scores

    const int b = blockIdx.x, h = blockIdx.y;
    const int tid = threadIdx.x, warp = tid >> 5, lane = tid & 31;
    const size_t base = (size_t)(b * NTOK) * DIMC + h * 64;

    const uint32_t qb = (uint32_t)__cvta_generic_to_shared(sQ);
    const uint32_t kb = (uint32_t)__cvta_generic_to_shared(sK);
    const uint32_t vb = (uint32_t)__cvta_generic_to_shared(sV);

    // load Q,K,V rows 0..48 (swizzled 128B rows)
    for (int t = tid; t < NTOK * 8; t += 128) {
        int r = t >> 3, g = t & 7;
        uint32_t off = (uint32_t)(r * 128 + ((g ^ (r & 7)) << 4));
        *(uint4*)(sQ + off) = *(const uint4*)&g_Q[base + (size_t)r * DIMC + g * 8];
        *(uint4*)(sK + off) = *(const uint4*)&g_K[base + (size_t)r * DIMC + g * 8];
        *(uint4*)(sV + off) = *(const uint4*)&g_V[base + (size_t)r * DIMC + g * 8];
    }
    // zero V pad rows 49..63 (PV k-dim padding safety)
    for (int t = tid; t < 15 * 8; t += 128) {
        int r = NTOK + (t >> 3), g = t & 7;
        uint32_t off = (uint32_t)(r * 128 + ((g ^ (r & 7)) << 4));
        *(uint4*)(sV + off) = make_uint4(0, 0, 0, 0);
    }
    __syncthreads();

    const int lane_r = lane & 15, halfA = lane >> 4;
    const int quad = lane >> 3, gsel = quad & 1, rsel = quad >> 1;
    const int r8 = lane >> 2, cp2 = (lane & 3) * 2;
    const int swA = lane_r & 7, sw8 = lane & 7;

    // ---- QK^T: warp computes rows 16w..16w+15 x all 64 cols ----
    {
        float acc[8][4];
#pragma unroll
        for (int nt = 0; nt < 8; ++nt)
#pragma unroll
            for (int c = 0; c < 4; ++c) acc[nt][c] = 0.f;

        const uint32_t aRowOff = qb + (uint32_t)((16 * warp + lane_r) * 128);
        uint32_t bRowOff[4];
#pragma unroll
        for (int pj = 0; pj < 4; ++pj)
            bRowOff[pj] = kb + (uint32_t)((16 * pj + rsel * 8 + sw8) * 128);

#pragma unroll
        for (int ks = 0; ks < 4; ++ks) {
            uint32_t a0, a1, a2, a3;
            ldsm_x4(a0, a1, a2, a3, aRowOff + (uint32_t)(((ks * 2 + halfA) ^ swA) << 4));
            const uint32_t gB = (uint32_t)(((ks * 2 + gsel) ^ sw8) << 4);
#pragma unroll
            for (int pj = 0; pj < 4; ++pj) {
                uint32_t b0, b1, b2, b3;
                ldsm_x4(b0, b1, b2, b3, bRowOff[pj] + gB);
                mma_f16(acc[2 * pj],     a0, a1, a2, a3, b0, b1);
                mma_f16(acc[2 * pj + 1], a0, a1, a2, a3, b2, b3);
            }
        }

        // epilogue: scale + bias + mask -> sS
        const float* gbias = g_bias + h * (NTOK * NTOK);
        const int i0 = 16 * warp + r8, i1 = i0 + 8;
#pragma unroll
        for (int nt = 0; nt < 8; ++nt) {
            int j0 = nt * 8 + cp2, j1 = j0 + 1;
            float v0 = -1e30f, v1 = -1e30f, v2 = -1e30f, v3 = -1e30f;
            if (i0 < NTOK) {
                if (j0 < NTOK) v0 = acc[nt][0] * SCALE + gbias[i0 * NTOK + j0];
                if (j1 < NTOK) v1 = acc[nt][1] * SCALE + gbias[i0 * NTOK + j1];
            }
            if (i1 < NTOK) {
                if (j0 < NTOK) v2 = acc[nt][2] * SCALE + gbias[i1 * NTOK + j0];
                if (j1 < NTOK) v3 = acc[nt][3] * SCALE + gbias[i1 * NTOK + j1];
            }
            sS[i0 * 66 + j0] = v0; sS[i0 * 66 + j1] = v1;
            sS[i1 * 66 + j0] = v2; sS[i1 * 66 + j1] = v3;
        }
    }
    __syncthreads();

    // ---- softmax rows, write P (half) into sQ region, swizzled ----
    for (int i = warp; i < NTOK; i += 4) {
        float v1 = sS[i * 66 + lane];
        float v2 = sS[i * 66 + lane + 32];
        float m = fmaxf(v1, v2);
#pragma unroll
        for (int o = 16; o > 0; o >>= 1) m = fmaxf(m, __shfl_xor_sync(0xFFFFFFFFu, m, o));
        float e1 = __expf(v1 - m), e2 = __expf(v2 - m);
        float s = e1 + e2;
#pragma unroll
        for (int o = 16; o > 0; o >>= 1) s += __shfl_xor_sync(0xFFFFFFFFu, s, o);
        float inv = 1.f / s;
        __half p1 = __float2half_rn(e1 * inv);
        __half p2 = __float2half_rn(e2 * inv);
        int j1 = lane, j2 = lane + 32;
        *(__half*)(sQ + i * 128 + (((j1 >> 3) ^ (i & 7)) << 4) + (j1 & 7) * 2) = p1;
        *(__half*)(sQ + i * 128 + (((j2 >> 3) ^ (i & 7)) << 4) + (j2 & 7) * 2) = p2;
    }
    __syncthreads();

    // ---- PV: out rows 16w..16w+15 x 64 dims ----
    {
        float acc[8][4];
#pragma unroll
        for (int nt = 0; nt < 8; ++nt)
#pragma unroll
            for (int c = 0; c < 4; ++c) acc[nt][c] = 0.f;

        const uint32_t aRowOff = qb + (uint32_t)((16 * warp + lane_r) * 128);

#pragma unroll
        for (int ks = 0; ks < 4; ++ks) {
            uint32_t a0, a1, a2, a3;
            ldsm_x4(a0, a1, a2, a3, aRowOff + (uint32_t)(((ks * 2 + halfA) ^ swA) << 4));
            // B from V via trans: thread row = 16ks + 8*gsel + (lane&7), granule = 2*pj + rsel
            const uint32_t tRow = (uint32_t)(16 * ks + 8 * gsel + sw8);
            const uint32_t vRow = vb + tRow * 128;
#pragma unroll
            for (int pj = 0; pj < 4; ++pj) {
                uint32_t b0, b1, b2, b3;
                ldsm_x4_t(b0, b1, b2, b3, vRow + (uint32_t)((((2 * pj + rsel) ^ sw8) << 4)));
                mma_f16(acc[2 * pj],     a0, a1, a2, a3, b0, b1);
                mma_f16(acc[2 * pj + 1], a0, a1, a2, a3, b2, b3);
            }
        }

        // store to g_B (half)
        const int i0 = 16 * warp + r8, i1 = i0 + 8;
#pragma unroll
        for (int nt = 0; nt < 8; ++nt) {
            int d = nt * 8 + cp2;
            if (i0 < NTOK) {
                __half2 o = __floats2half2_rn(acc[nt][0], acc[nt][1]);
                *(__half2*)&g_B[base + (size_t)i0 * DIMC + d] = o;
            }
            if (i1 < NTOK) {
                __half2 o = __floats2half2_rn(acc[nt][2], acc[nt][3]);
                *(__half2*)&g_B[base + (size_t)i1 * DIMC + d] = o;
            }
        }
    }
}

// ---------------- launch ----------------
extern "C" void kernel_launch(void* const* d_in, const int* in_sizes, int n_in,
                              void* d_out, int out_size) {
    const float* landmark = (const float*)d_in[0];
    const float* image    = (const float*)d_in[1];
    const float* Wq = (const float*)d_in[2];
    const float* bq = (const float*)d_in[3];
    const float* Wk = (const float*)d_in[4];
    const float* bk = (const float*)d_in[5];
    const float* Wv = (const float*)d_in[6];
    const float* bv = (const float*)d_in[7];
    const float* Wo = (const float*)d_in[8];
    const float* bo = (const float*)d_in[9];
    const float* bt = (const float*)d_in[10];
    const int*   ri = (const int*)d_in[11];
    float* out = (float*)d_out;

    cudaFuncSetAttribute(gemm_h, cudaFuncAttributeMaxDynamicSharedMemorySize, SMEMSZ);

    dim3 gg(DIMC / BN, MROWS / BM);   // (8, 392)

    f2h_inputs<<<8192, 256>>>(landmark, image);
    f2h_weights_bias<<<512, 256>>>(Wq, Wk, Wv, Wo, bt, ri);
    gemm_h<<<gg, 256, SMEMSZ>>>(bq, nullptr, 0, 0, 1);   // Q
    gemm_h<<<gg, 256, SMEMSZ>>>(bk, nullptr, 1, 1, 2);   // K
    gemm_h<<<gg, 256, SMEMSZ>>>(bv, nullptr, 1, 2, 3);   // V
    attn_mma<<<dim3(BATCH, HEADS), 128>>>();
    gemm_h<<<gg, 256, SMEMSZ>>>(bo, out, 1, 3, 0);       // O
}